// round 13
// baseline (speedup 1.0000x reference)
#include <cuda_runtime.h>
#include <cuda_fp16.h>
#include <cstdint>

// Problem constants
#define B_   32
#define S_   2048
#define D_   1024
#define M_   (B_ * S_)     // 65536
#define NCB  8             // 128-wide column blocks over D

// GEMM tiling (fp16) — R9-proven shape: 128x128 CTA tile, 64x32 warp tile,
// 8 consumer warps + 1 producer warp, mbarrier pipeline, 2 CTA/SM.
#define BM   128
#define BN   128
#define BKH  64            // K halves per stage (128-byte rows)
#define NKS  16            // k-steps per tile
#define NTHR 288           // 8 consumer warps + 1 producer warp

// Scratch (device globals; allocation-free rule)
__device__ float  g_target2[B_ * D_];
__device__ float  g_score_part[NCB * M_];
__device__ float  g_wpart[64 * B_ * D_];
__device__ float  g_weighted[B_ * D_];
__device__ __half g_ctx_h[(size_t)M_ * D_];   // 128MB fp16 context
__device__ __half g_wc_h[D_ * D_];            // 2MB fp16 W_c

// ---------------------------------------------------------------------------
// PTX helpers (generic sm_80/90 subset only — no tcgen05 on compute_103 PTX)
// ---------------------------------------------------------------------------
__device__ __forceinline__ uint32_t smem_u32(const void* p) {
    uint32_t a;
    asm("{ .reg .u64 t; cvta.to.shared.u64 t, %1; cvt.u32.u64 %0, t; }"
        : "=r"(a) : "l"(p));
    return a;
}

__device__ __forceinline__ void cp16(uint32_t saddr, const void* gaddr) {
    asm volatile("cp.async.cg.shared.global [%0], [%1], 16;"
                 :: "r"(saddr), "l"(gaddr));
}

// cp.async with 256B L2 prefetch window: pulls the NEXT k-step's 128B row
// segment into L2 while streaming this one (stride-contiguous A rows).
__device__ __forceinline__ void cp16p(uint32_t saddr, const void* gaddr) {
    asm volatile("cp.async.cg.shared.global.L2::256B [%0], [%1], 16;"
                 :: "r"(saddr), "l"(gaddr));
}

__device__ __forceinline__ void ldm4(uint32_t addr, uint32_t& r0, uint32_t& r1,
                                     uint32_t& r2, uint32_t& r3) {
    asm volatile("ldmatrix.sync.aligned.m8n8.x4.shared.b16 {%0,%1,%2,%3}, [%4];"
                 : "=r"(r0), "=r"(r1), "=r"(r2), "=r"(r3) : "r"(addr));
}

__device__ __forceinline__ void mma_f16(float* d, const uint32_t* a, const uint32_t* b) {
    asm volatile(
        "mma.sync.aligned.m16n8k16.row.col.f32.f16.f16.f32 "
        "{%0,%1,%2,%3}, {%4,%5,%6,%7}, {%8,%9}, {%0,%1,%2,%3};"
        : "+f"(d[0]), "+f"(d[1]), "+f"(d[2]), "+f"(d[3])
        : "r"(a[0]), "r"(a[1]), "r"(a[2]), "r"(a[3]), "r"(b[0]), "r"(b[1]));
}

__device__ __forceinline__ float fast_tanh(float x) {
    float y;
    asm("tanh.approx.f32 %0, %1;" : "=f"(y) : "f"(x));
    return y;
}

__device__ __forceinline__ void mbar_init(uint32_t a, uint32_t n) {
    asm volatile("mbarrier.init.shared.b64 [%0], %1;" :: "r"(a), "r"(n) : "memory");
}

__device__ __forceinline__ void mbar_arrive(uint32_t a) {
    asm volatile("mbarrier.arrive.shared.b64 _, [%0];" :: "r"(a) : "memory");
}

__device__ __forceinline__ void cp_arrive_noinc(uint32_t a) {
    asm volatile("cp.async.mbarrier.arrive.noinc.shared.b64 [%0];"
                 :: "r"(a) : "memory");
}

__device__ __forceinline__ void mbar_wait(uint32_t mbar, uint32_t parity) {
    uint32_t done;
    asm volatile(
        "{\n\t.reg .pred p;\n\t"
        "mbarrier.try_wait.parity.acquire.cta.shared::cta.b64 p, [%1], %2;\n\t"
        "selp.b32 %0, 1, 0, p;\n\t}"
        : "=r"(done) : "r"(mbar), "r"(parity) : "memory");
    if (!done) {
        asm volatile(
            "{\n\t.reg .pred P1;\n\t"
            "WL%=:\n\t"
            "mbarrier.try_wait.parity.acquire.cta.shared::cta.b64 P1, [%0], %1, 0x989680;\n\t"
            "@P1 bra.uni WD%=;\n\t"
            "bra.uni WL%=;\n\t"
            "WD%=:\n\t}"
            :: "r"(mbar), "r"(parity) : "memory");
    }
}

// ---------------------------------------------------------------------------
// Kernel 0: fused prep — target blocks (0..127) + fp16 conversion (32B/thread).
// ---------------------------------------------------------------------------
#define TGT_BLOCKS 128
#define CTX_BLOCKS ((int)((size_t)M_ * D_ / 8 / 256))   // 32768
#define WC_BLOCKS  (D_ * D_ / 8 / 256)                  // 512
#define PREP_BLOCKS (TGT_BLOCKS + CTX_BLOCKS + WC_BLOCKS)

__global__ __launch_bounds__(256) void prep_kernel(
    const float* __restrict__ ctx, const float* __restrict__ wc,
    const float* __restrict__ x, const float* __restrict__ W_in,
    const float* __restrict__ b_c)
{
    __shared__ float sx[32][129];
    __shared__ float sw[8][129];
    const int bid = blockIdx.x;
    const int tid = threadIdx.x;

    if (bid < TGT_BLOCKS) {
        // ---- target2[b][j] = sum_k x[b][k] * W_in[j][k] + b_c[j] ----
        int b = tid >> 3, jj = tid & 7;
        int j = bid * 8 + jj;
        float acc = 0.f;
        for (int k0 = 0; k0 < D_; k0 += 128) {
            #pragma unroll
            for (int i = 0; i < 16; i++) {
                int f = tid + i * 256;
                int r = f >> 7, c = f & 127;
                sx[r][c] = x[r * D_ + k0 + c];
            }
            #pragma unroll
            for (int i = 0; i < 4; i++) {
                int f = tid + i * 256;
                int r = f >> 7, c = f & 127;
                sw[r][c] = W_in[(size_t)(bid * 8 + r) * D_ + k0 + c];
            }
            __syncthreads();
            #pragma unroll 8
            for (int k = 0; k < 128; k++) acc += sx[b][k] * sw[jj][k];
            __syncthreads();
        }
        g_target2[b * D_ + j] = acc + b_c[j];
    } else {
        // ---- fp32 -> fp16 conversion, 8 floats (32B) per thread ----
        int cb = bid - TGT_BLOCKS;
        const float* src;
        __half* dst;
        size_t i;
        if (cb < CTX_BLOCKS) {
            i = ((size_t)cb * 256 + tid) * 8;
            src = ctx; dst = g_ctx_h;
        } else {
            i = ((size_t)(cb - CTX_BLOCKS) * 256 + tid) * 8;
            src = wc; dst = g_wc_h;
        }
        float4 v0 = *(const float4*)(src + i);
        float4 v1 = *(const float4*)(src + i + 4);
        __half2 h0 = __floats2half2_rn(v0.x, v0.y);
        __half2 h1 = __floats2half2_rn(v0.z, v0.w);
        __half2 h2 = __floats2half2_rn(v1.x, v1.y);
        __half2 h3 = __floats2half2_rn(v1.z, v1.w);
        uint4 o;
        o.x = *(uint32_t*)&h0; o.y = *(uint32_t*)&h1;
        o.z = *(uint32_t*)&h2; o.w = *(uint32_t*)&h3;
        *(uint4*)(dst + i) = o;
    }
}

// ---------------------------------------------------------------------------
// Kernel 2: warp-specialized fp16 mma score GEMM
// (R12 + L2::256B prefetch on producer cp.async).
// ---------------------------------------------------------------------------
// smem (from 1024-aligned base):
//   0: s_tgt[128]  512: s_wv[128]  1024: s_red[512 floats]
//   3072: full[3] mbars  3104: empty[3] mbars  4096: tiles (3 x 32KB)
#define OFF_TILE     4096
#define STAGE_STRIDE 32768
#define SMEM_NEED    (OFF_TILE + 3 * STAGE_STRIDE)
#define SMEM_BYTES   (SMEM_NEED + 1024)

__global__ __launch_bounds__(NTHR, 2) void score_gemm_mma(
    const float* __restrict__ w_v)
{
    extern __shared__ char dynsmem[];
    uint32_t sbm = smem_u32(dynsmem);
    uint32_t ab = (sbm + 1023u) & ~1023u;
    char* abp = dynsmem + (ab - sbm);

    const int bn = blockIdx.x;       // 0..7 (fast dim -> A-tile L2 sharing)
    const int bm = blockIdx.y;       // 0..511
    const int tid = threadIdx.x;
    const int wid = tid >> 5, lid = tid & 31;
    const int b = bm >> 4;

    float* s_tgt = (float*)(abp);
    float* s_wv  = (float*)(abp + 512);
    float* s_red = (float*)(abp + 1024);
    const uint32_t fullb  = ab + 3072;
    const uint32_t emptyb = ab + 3104;
    const uint32_t tbase = ab + OFF_TILE;

    if (tid == 0) {
        #pragma unroll
        for (int s = 0; s < 3; s++) {
            mbar_init(fullb + s * 8u, 32);    // producer lanes (cp-completion)
            mbar_init(emptyb + s * 8u, 256);  // consumer threads
        }
    }
    if (tid < 128) {
        s_tgt[tid] = g_target2[b * D_ + bn * BN + tid];
        s_wv[tid]  = w_v[bn * BN + tid];
    }
    __syncthreads();   // all 288: mbar init + s_tgt visible

    if (wid == 8) {
        // ---------------- producer warp ----------------
        const int r0 = lid >> 3;                       // 0..3
        const int kq = lid & 7;
        const uint32_t swzE = ((uint32_t)kq * 16) ^ ((uint32_t)r0 << 4);
        const uint32_t sEA = tbase + (uint32_t)r0 * 128 + swzE;
        const uint32_t sOA = (sEA ^ 64u) + 512u;
        const uint32_t sEB = sEA + 16384u;
        const uint32_t sOB = sOA + 16384u;
        const __half* gA = g_ctx_h + (size_t)bm * BM * D_ + (size_t)r0 * D_ + kq * 8;
        const __half* gB = g_wc_h + (size_t)bn * BN * D_ + (size_t)r0 * D_ + kq * 8;

        uint32_t pslot = 0;
        int pstage = 0, pphase = 1;   // phase=1: first 3 empty-waits pass
        for (int ks = 0; ks < NKS; ks++) {
            mbar_wait(emptyb + (uint32_t)pstage * 8u, (uint32_t)pphase);
            #pragma unroll
            for (int j = 0; j < 16; j++) {
                cp16p(sEA + pslot + (uint32_t)j * 1024u, gA + (size_t)j * 8192);
                cp16p(sOA + pslot + (uint32_t)j * 1024u, gA + (size_t)j * 8192 + 4096);
                cp16p(sEB + pslot + (uint32_t)j * 1024u, gB + (size_t)j * 8192);
                cp16p(sOB + pslot + (uint32_t)j * 1024u, gB + (size_t)j * 8192 + 4096);
            }
            cp_arrive_noinc(fullb + (uint32_t)pstage * 8u);
            gA += BKH; gB += BKH;
            pstage++; pslot += STAGE_STRIDE;
            if (pstage == 3) { pstage = 0; pslot = 0; pphase ^= 1; }
        }
    } else {
        // ---------------- consumer warps ----------------
        const int warp_m = wid & 1;
        const int warp_n = wid >> 1;
        const int r15 = lid & 15, q = lid >> 4;
        const uint32_t swz = ((uint32_t)(r15 & 7)) << 4;
        const uint32_t loffA = (uint32_t)((warp_m * 64 + r15) * 128) + (((uint32_t)q * 16) ^ swz);
        const uint32_t loffB = (uint32_t)((warp_n * 32 + r15) * 128) + (((uint32_t)q * 16) ^ swz) + 16384u;
        uint32_t adrA[4], adrB[4];
        #pragma unroll
        for (int c = 0; c < 4; c++) {
            adrA[c] = (tbase + loffA) ^ ((uint32_t)c << 5);
            adrB[c] = (tbase + loffB) ^ ((uint32_t)c << 5);
        }

        float acc[4][4][4];
        #pragma unroll
        for (int mf = 0; mf < 4; mf++)
            #pragma unroll
            for (int nf = 0; nf < 4; nf++)
                #pragma unroll
                for (int r = 0; r < 4; r++) acc[mf][nf][r] = 0.f;

        uint32_t soff = 0;
        int cstage = 0, cphase = 0;
        for (int ks = 0; ks < NKS; ks++) {
            mbar_wait(fullb + (uint32_t)cstage * 8u, (uint32_t)cphase);
            #pragma unroll
            for (int c = 0; c < 4; c++) {
                uint32_t a[4][4], bfr[4][2];
                #pragma unroll
                for (int mf = 0; mf < 4; mf++)
                    ldm4(adrA[c] + soff + (uint32_t)mf * 2048u,
                         a[mf][0], a[mf][1], a[mf][2], a[mf][3]);
                #pragma unroll
                for (int p = 0; p < 2; p++) {
                    uint32_t t0, t1, t2, t3;
                    ldm4(adrB[c] + soff + (uint32_t)p * 2048u, t0, t1, t2, t3);
                    bfr[2 * p][0]     = t0; bfr[2 * p][1]     = t2;
                    bfr[2 * p + 1][0] = t1; bfr[2 * p + 1][1] = t3;
                }
                // Early empty-arrive: after the LAST chunk's LDSMs the stage
                // lives entirely in registers.
                if (c == 3) mbar_arrive(emptyb + (uint32_t)cstage * 8u);
                #pragma unroll
                for (int mf = 0; mf < 4; mf++)
                    #pragma unroll
                    for (int nf = 0; nf < 4; nf++)
                        mma_f16(acc[mf][nf], a[mf], bfr[nf]);
            }
            cstage++; soff += STAGE_STRIDE;
            if (cstage == 3) { cstage = 0; soff = 0; cphase ^= 1; }
        }

        // Epilogue: sum_n tanh(acc + tgt[n]) * wv[n]
        const int g = lid >> 2, tig = lid & 3;
        #pragma unroll
        for (int mf = 0; mf < 4; mf++) {
            float p0 = 0.f, p1 = 0.f;
            #pragma unroll
            for (int nf = 0; nf < 4; nf++) {
                int n0 = warp_n * 32 + nf * 8 + 2 * tig;
                float t0 = s_tgt[n0], t1 = s_tgt[n0 + 1];
                float v0 = s_wv[n0],  v1 = s_wv[n0 + 1];
                p0 += fast_tanh(acc[mf][nf][0] + t0) * v0;
                p0 += fast_tanh(acc[mf][nf][1] + t1) * v1;
                p1 += fast_tanh(acc[mf][nf][2] + t0) * v0;
                p1 += fast_tanh(acc[mf][nf][3] + t1) * v1;
            }
            p0 += __shfl_xor_sync(0xFFFFFFFF, p0, 1);
            p0 += __shfl_xor_sync(0xFFFFFFFF, p0, 2);
            p1 += __shfl_xor_sync(0xFFFFFFFF, p1, 1);
            p1 += __shfl_xor_sync(0xFFFFFFFF, p1, 2);
            if (tig == 0) {
                int row = warp_m * 64 + mf * 16 + g;
                s_red[row * 4 + warp_n] = p0;
                s_red[(row + 8) * 4 + warp_n] = p1;
            }
        }
        asm volatile("bar.sync 1, 256;" ::: "memory");   // consumers only
        if (tid < BM) {
            float s = s_red[tid * 4] + s_red[tid * 4 + 1] +
                      s_red[tid * 4 + 2] + s_red[tid * 4 + 3];
            g_score_part[(size_t)bn * M_ + bm * BM + tid] = s;
        }
    }
}

// ---------------------------------------------------------------------------
// Kernel 3: softmax over S per batch
// ---------------------------------------------------------------------------
__global__ __launch_bounds__(1024) void softmax_kernel(float* __restrict__ attn_out)
{
    __shared__ float red[1024];
    const int b = blockIdx.x;
    const int tid = threadIdx.x;

    float s0 = 0.f, s1 = 0.f;
    #pragma unroll
    for (int p = 0; p < NCB; p++) {
        s0 += g_score_part[(size_t)p * M_ + b * S_ + tid];
        s1 += g_score_part[(size_t)p * M_ + b * S_ + 1024 + tid];
    }
    float m = fmaxf(s0, s1);
    red[tid] = m;
    __syncthreads();
    for (int st = 512; st > 0; st >>= 1) {
        if (tid < st) red[tid] = fmaxf(red[tid], red[tid + st]);
        __syncthreads();
    }
    m = red[0];
    __syncthreads();
    float e0 = expf(s0 - m), e1 = expf(s1 - m);
    red[tid] = e0 + e1;
    __syncthreads();
    for (int st = 512; st > 0; st >>= 1) {
        if (tid < st) red[tid] += red[tid + st];
        __syncthreads();
    }
    float inv = 1.f / red[0];
    attn_out[b * S_ + tid] = e0 * inv;
    attn_out[b * S_ + 1024 + tid] = e1 * inv;
}

// ---------------------------------------------------------------------------
// Kernel 4: weighted partials, uint4 (16B) loads.
// grid (64 s-chunks, 32 b) x 256. Thread: col-group c = tid&127 (8 halves),
// row parity p = tid>>7; even/odd rows combined through smem.
// ---------------------------------------------------------------------------
__global__ __launch_bounds__(256) void weighted_kernel(const float* __restrict__ attn)
{
    __shared__ float comb[128][8];
    const int sc = blockIdx.x;   // 0..63, 32 rows each
    const int b = blockIdx.y;
    const int tid = threadIdx.x;
    const int c = tid & 127;     // col group (8 halves = 16B)
    const int p = tid >> 7;      // row parity

    float acc[8];
    #pragma unroll
    for (int i = 0; i < 8; i++) acc[i] = 0.f;

    const __half* ctxb = g_ctx_h + ((size_t)b * S_ + sc * 32) * D_ + c * 8;
    const float* aw = attn + b * S_ + sc * 32;
    #pragma unroll 4
    for (int s = p; s < 32; s += 2) {
        float w = aw[s];
        uint4 v = *(const uint4*)(ctxb + (size_t)s * D_);
        const __half2* h = (const __half2*)&v;
        #pragma unroll
        for (int i = 0; i < 4; i++) {
            float2 f = __half22float2(h[i]);
            acc[2 * i]     += w * f.x;
            acc[2 * i + 1] += w * f.y;
        }
    }
    if (p == 0) {
        #pragma unroll
        for (int i = 0; i < 8; i++) comb[c][i] = acc[i];
    }
    __syncthreads();
    if (p == 1) {
        float* dst = g_wpart + ((size_t)sc * B_ + b) * D_ + c * 8;
        float4 o0, o1;
        o0.x = comb[c][0] + acc[0]; o0.y = comb[c][1] + acc[1];
        o0.z = comb[c][2] + acc[2]; o0.w = comb[c][3] + acc[3];
        o1.x = comb[c][4] + acc[4]; o1.y = comb[c][5] + acc[5];
        o1.z = comb[c][6] + acc[6]; o1.w = comb[c][7] + acc[7];
        *(float4*)dst = o0;
        *(float4*)(dst + 4) = o1;
    }
}

__global__ __launch_bounds__(256) void wreduce_kernel()
{
    int i = blockIdx.x * 256 + threadIdx.x;
    float4 s = make_float4(0.f, 0.f, 0.f, 0.f);
    #pragma unroll
    for (int p = 0; p < 64; p++) {
        float4 v = ((const float4*)g_wpart)[(size_t)p * (B_ * D_ / 4) + i];
        s.x += v.x; s.y += v.y; s.z += v.z; s.w += v.w;
    }
    ((float4*)g_weighted)[i] = s;
}

// ---------------------------------------------------------------------------
// Kernel 5: h_tilde = tanh([weighted, x] @ W_out^T)
// 64 blocks x 16 j-columns; 2 outputs/thread (sc-load reuse).
// ---------------------------------------------------------------------------
__global__ __launch_bounds__(256) void out_kernel(
    const float* __restrict__ x, const float* __restrict__ W_out,
    float* __restrict__ out)
{
    __shared__ float sc[32][132];
    __shared__ float sw[16][132];
    int tid = threadIdx.x;
    int b = tid >> 3, jj = tid & 7;
    int j0 = blockIdx.x * 16 + jj * 2;
    float acc0 = 0.f, acc1 = 0.f;
    for (int k0 = 0; k0 < 2 * D_; k0 += 128) {
        // sc: 32 rows x 128 cols = 1024 float4, 4 per thread
        #pragma unroll
        for (int i = 0; i < 4; i++) {
            int f = tid + i * 256;
            int r = f >> 5, c4 = f & 31;
            int k = k0 + c4 * 4;
            float4 v = (k < D_)
                ? *(const float4*)(g_weighted + r * D_ + k)
                : *(const float4*)(x + r * D_ + (k - D_));
            *(float4*)&sc[r][c4 * 4] = v;
        }
        // sw: 16 rows x 128 cols = 512 float4, 2 per thread
        #pragma unroll
        for (int i = 0; i < 2; i++) {
            int f = tid + i * 256;
            int r = f >> 5, c4 = f & 31;
            float4 v = *(const float4*)(W_out + (size_t)(blockIdx.x * 16 + r) * (2 * D_) + k0 + c4 * 4);
            *(float4*)&sw[r][c4 * 4] = v;
        }
        __syncthreads();
        #pragma unroll 8
        for (int k = 0; k < 128; k++) {
            float s = sc[b][k];
            acc0 += s * sw[jj * 2][k];
            acc1 += s * sw[jj * 2 + 1][k];
        }
        __syncthreads();
    }
    out[b * D_ + j0] = tanhf(acc0);
    out[b * D_ + j0 + 1] = tanhf(acc1);
}

// ---------------------------------------------------------------------------
// Launch. Inputs: x, context, W_in, W_c, b_c, w_v, W_out
// Output: h_tilde [32,1024] then attn_w [32,2048]
// ---------------------------------------------------------------------------
extern "C" void kernel_launch(void* const* d_in, const int* in_sizes, int n_in,
                              void* d_out, int out_size)
{
    const float* x       = (const float*)d_in[0];
    const float* context = (const float*)d_in[1];
    const float* W_in    = (const float*)d_in[2];
    const float* W_c     = (const float*)d_in[3];
    const float* b_c     = (const float*)d_in[4];
    const float* w_v     = (const float*)d_in[5];
    const float* W_out   = (const float*)d_in[6];
    float* out = (float*)d_out;
    float* attn_out = out + B_ * D_;

    cudaFuncSetAttribute(score_gemm_mma,
                         cudaFuncAttributeMaxDynamicSharedMemorySize, SMEM_BYTES);

    prep_kernel<<<PREP_BLOCKS, 256>>>(context, W_c, x, W_in, b_c);
    score_gemm_mma<<<dim3(NCB, M_ / BM), NTHR, SMEM_BYTES>>>(w_v);
    softmax_kernel<<<B_, 1024>>>(attn_out);
    weighted_kernel<<<dim3(64, B_), 256>>>(attn_out);
    wreduce_kernel<<<32, 256>>>();
    out_kernel<<<64, 256>>>(x, W_out, out);
}

// round 14
// speedup vs baseline: 1.0421x; 1.0421x over previous
#include <cuda_runtime.h>
#include <cuda_fp16.h>
#include <cstdint>

// Problem constants
#define B_   32
#define S_   2048
#define D_   1024
#define M_   (B_ * S_)     // 65536
#define NCB  8             // 128-wide column blocks over D

// GEMM tiling (fp16) — R9-proven shape: 128x128 CTA tile, 64x32 warp tile,
// 8 consumer warps + 1 producer warp, mbarrier pipeline, 2 CTA/SM.
#define BM   128
#define BN   128
#define BKH  64            // K halves per stage (128-byte rows)
#define NKS  16            // k-steps per tile
#define NTHR 288           // 8 consumer warps + 1 producer warp

// Scratch (device globals; allocation-free rule)
__device__ float  g_target2[B_ * D_];
__device__ float  g_score_part[NCB * M_];
__device__ float  g_wpart[16 * B_ * D_];
__device__ float  g_weighted[B_ * D_];
__device__ __half g_ctx_h[(size_t)M_ * D_];   // 128MB fp16 context
__device__ __half g_wc_h[D_ * D_];            // 2MB fp16 W_c

// ---------------------------------------------------------------------------
// PTX helpers (generic sm_80/90 subset only — no tcgen05 on compute_103 PTX)
// ---------------------------------------------------------------------------
__device__ __forceinline__ uint32_t smem_u32(const void* p) {
    uint32_t a;
    asm("{ .reg .u64 t; cvta.to.shared.u64 t, %1; cvt.u32.u64 %0, t; }"
        : "=r"(a) : "l"(p));
    return a;
}

__device__ __forceinline__ void cp16(uint32_t saddr, const void* gaddr) {
    asm volatile("cp.async.cg.shared.global [%0], [%1], 16;"
                 :: "r"(saddr), "l"(gaddr));
}

__device__ __forceinline__ void ldm4(uint32_t addr, uint32_t& r0, uint32_t& r1,
                                     uint32_t& r2, uint32_t& r3) {
    asm volatile("ldmatrix.sync.aligned.m8n8.x4.shared.b16 {%0,%1,%2,%3}, [%4];"
                 : "=r"(r0), "=r"(r1), "=r"(r2), "=r"(r3) : "r"(addr));
}

__device__ __forceinline__ void mma_f16(float* d, const uint32_t* a, const uint32_t* b) {
    asm volatile(
        "mma.sync.aligned.m16n8k16.row.col.f32.f16.f16.f32 "
        "{%0,%1,%2,%3}, {%4,%5,%6,%7}, {%8,%9}, {%0,%1,%2,%3};"
        : "+f"(d[0]), "+f"(d[1]), "+f"(d[2]), "+f"(d[3])
        : "r"(a[0]), "r"(a[1]), "r"(a[2]), "r"(a[3]), "r"(b[0]), "r"(b[1]));
}

__device__ __forceinline__ float fast_tanh(float x) {
    float y;
    asm("tanh.approx.f32 %0, %1;" : "=f"(y) : "f"(x));
    return y;
}

__device__ __forceinline__ void mbar_init(uint32_t a, uint32_t n) {
    asm volatile("mbarrier.init.shared.b64 [%0], %1;" :: "r"(a), "r"(n) : "memory");
}

__device__ __forceinline__ void mbar_arrive(uint32_t a) {
    asm volatile("mbarrier.arrive.shared.b64 _, [%0];" :: "r"(a) : "memory");
}

__device__ __forceinline__ void cp_arrive_noinc(uint32_t a) {
    asm volatile("cp.async.mbarrier.arrive.noinc.shared.b64 [%0];"
                 :: "r"(a) : "memory");
}

__device__ __forceinline__ void mbar_wait(uint32_t mbar, uint32_t parity) {
    uint32_t done;
    asm volatile(
        "{\n\t.reg .pred p;\n\t"
        "mbarrier.try_wait.parity.acquire.cta.shared::cta.b64 p, [%1], %2;\n\t"
        "selp.b32 %0, 1, 0, p;\n\t}"
        : "=r"(done) : "r"(mbar), "r"(parity) : "memory");
    if (!done) {
        asm volatile(
            "{\n\t.reg .pred P1;\n\t"
            "WL%=:\n\t"
            "mbarrier.try_wait.parity.acquire.cta.shared::cta.b64 P1, [%0], %1, 0x989680;\n\t"
            "@P1 bra.uni WD%=;\n\t"
            "bra.uni WL%=;\n\t"
            "WD%=:\n\t}"
            :: "r"(mbar), "r"(parity) : "memory");
    }
}

// ---------------------------------------------------------------------------
// Kernel 0: fused prep — target blocks (0..127) + fp16 conversion (32B/thread).
// ---------------------------------------------------------------------------
#define TGT_BLOCKS 128
#define CTX_BLOCKS ((int)((size_t)M_ * D_ / 8 / 256))   // 32768
#define WC_BLOCKS  (D_ * D_ / 8 / 256)                  // 512
#define PREP_BLOCKS (TGT_BLOCKS + CTX_BLOCKS + WC_BLOCKS)

__global__ __launch_bounds__(256) void prep_kernel(
    const float* __restrict__ ctx, const float* __restrict__ wc,
    const float* __restrict__ x, const float* __restrict__ W_in,
    const float* __restrict__ b_c)
{
    __shared__ float sx[32][129];
    __shared__ float sw[8][129];
    const int bid = blockIdx.x;
    const int tid = threadIdx.x;

    if (bid < TGT_BLOCKS) {
        // ---- target2[b][j] = sum_k x[b][k] * W_in[j][k] + b_c[j] ----
        int b = tid >> 3, jj = tid & 7;
        int j = bid * 8 + jj;
        float acc = 0.f;
        for (int k0 = 0; k0 < D_; k0 += 128) {
            #pragma unroll
            for (int i = 0; i < 16; i++) {
                int f = tid + i * 256;
                int r = f >> 7, c = f & 127;
                sx[r][c] = x[r * D_ + k0 + c];
            }
            #pragma unroll
            for (int i = 0; i < 4; i++) {
                int f = tid + i * 256;
                int r = f >> 7, c = f & 127;
                sw[r][c] = W_in[(size_t)(bid * 8 + r) * D_ + k0 + c];
            }
            __syncthreads();
            #pragma unroll 8
            for (int k = 0; k < 128; k++) acc += sx[b][k] * sw[jj][k];
            __syncthreads();
        }
        g_target2[b * D_ + j] = acc + b_c[j];
    } else {
        // ---- fp32 -> fp16 conversion, 8 floats (32B) per thread ----
        int cb = bid - TGT_BLOCKS;
        const float* src;
        __half* dst;
        size_t i;
        if (cb < CTX_BLOCKS) {
            i = ((size_t)cb * 256 + tid) * 8;
            src = ctx; dst = g_ctx_h;
        } else {
            i = ((size_t)(cb - CTX_BLOCKS) * 256 + tid) * 8;
            src = wc; dst = g_wc_h;
        }
        float4 v0 = *(const float4*)(src + i);
        float4 v1 = *(const float4*)(src + i + 4);
        __half2 h0 = __floats2half2_rn(v0.x, v0.y);
        __half2 h1 = __floats2half2_rn(v0.z, v0.w);
        __half2 h2 = __floats2half2_rn(v1.x, v1.y);
        __half2 h3 = __floats2half2_rn(v1.z, v1.w);
        uint4 o;
        o.x = *(uint32_t*)&h0; o.y = *(uint32_t*)&h1;
        o.z = *(uint32_t*)&h2; o.w = *(uint32_t*)&h3;
        *(uint4*)(dst + i) = o;
    }
}

// ---------------------------------------------------------------------------
// Kernel 2: warp-specialized fp16 mma score GEMM (R12 exact: plain cp.async,
// early empty-arrive; NO L2 prefetch hint — it polluted the shared-A L2 set).
// ---------------------------------------------------------------------------
// smem (from 1024-aligned base):
//   0: s_tgt[128]  512: s_wv[128]  1024: s_red[512 floats]
//   3072: full[3] mbars  3104: empty[3] mbars  4096: tiles (3 x 32KB)
#define OFF_TILE     4096
#define STAGE_STRIDE 32768
#define SMEM_NEED    (OFF_TILE + 3 * STAGE_STRIDE)
#define SMEM_BYTES   (SMEM_NEED + 1024)

__global__ __launch_bounds__(NTHR, 2) void score_gemm_mma(
    const float* __restrict__ w_v)
{
    extern __shared__ char dynsmem[];
    uint32_t sbm = smem_u32(dynsmem);
    uint32_t ab = (sbm + 1023u) & ~1023u;
    char* abp = dynsmem + (ab - sbm);

    const int bn = blockIdx.x;       // 0..7 (fast dim -> A-tile L2 sharing)
    const int bm = blockIdx.y;       // 0..511
    const int tid = threadIdx.x;
    const int wid = tid >> 5, lid = tid & 31;
    const int b = bm >> 4;

    float* s_tgt = (float*)(abp);
    float* s_wv  = (float*)(abp + 512);
    float* s_red = (float*)(abp + 1024);
    const uint32_t fullb  = ab + 3072;
    const uint32_t emptyb = ab + 3104;
    const uint32_t tbase = ab + OFF_TILE;

    if (tid == 0) {
        #pragma unroll
        for (int s = 0; s < 3; s++) {
            mbar_init(fullb + s * 8u, 32);    // producer lanes (cp-completion)
            mbar_init(emptyb + s * 8u, 256);  // consumer threads
        }
    }
    if (tid < 128) {
        s_tgt[tid] = g_target2[b * D_ + bn * BN + tid];
        s_wv[tid]  = w_v[bn * BN + tid];
    }
    __syncthreads();   // all 288: mbar init + s_tgt visible

    if (wid == 8) {
        // ---------------- producer warp ----------------
        const int r0 = lid >> 3;                       // 0..3
        const int kq = lid & 7;
        const uint32_t swzE = ((uint32_t)kq * 16) ^ ((uint32_t)r0 << 4);
        const uint32_t sEA = tbase + (uint32_t)r0 * 128 + swzE;
        const uint32_t sOA = (sEA ^ 64u) + 512u;
        const uint32_t sEB = sEA + 16384u;
        const uint32_t sOB = sOA + 16384u;
        const __half* gA = g_ctx_h + (size_t)bm * BM * D_ + (size_t)r0 * D_ + kq * 8;
        const __half* gB = g_wc_h + (size_t)bn * BN * D_ + (size_t)r0 * D_ + kq * 8;

        uint32_t pslot = 0;
        int pstage = 0, pphase = 1;   // phase=1: first 3 empty-waits pass
        for (int ks = 0; ks < NKS; ks++) {
            mbar_wait(emptyb + (uint32_t)pstage * 8u, (uint32_t)pphase);
            #pragma unroll
            for (int j = 0; j < 16; j++) {
                cp16(sEA + pslot + (uint32_t)j * 1024u, gA + (size_t)j * 8192);
                cp16(sOA + pslot + (uint32_t)j * 1024u, gA + (size_t)j * 8192 + 4096);
                cp16(sEB + pslot + (uint32_t)j * 1024u, gB + (size_t)j * 8192);
                cp16(sOB + pslot + (uint32_t)j * 1024u, gB + (size_t)j * 8192 + 4096);
            }
            cp_arrive_noinc(fullb + (uint32_t)pstage * 8u);
            gA += BKH; gB += BKH;
            pstage++; pslot += STAGE_STRIDE;
            if (pstage == 3) { pstage = 0; pslot = 0; pphase ^= 1; }
        }
    } else {
        // ---------------- consumer warps ----------------
        const int warp_m = wid & 1;
        const int warp_n = wid >> 1;
        const int r15 = lid & 15, q = lid >> 4;
        const uint32_t swz = ((uint32_t)(r15 & 7)) << 4;
        const uint32_t loffA = (uint32_t)((warp_m * 64 + r15) * 128) + (((uint32_t)q * 16) ^ swz);
        const uint32_t loffB = (uint32_t)((warp_n * 32 + r15) * 128) + (((uint32_t)q * 16) ^ swz) + 16384u;
        uint32_t adrA[4], adrB[4];
        #pragma unroll
        for (int c = 0; c < 4; c++) {
            adrA[c] = (tbase + loffA) ^ ((uint32_t)c << 5);
            adrB[c] = (tbase + loffB) ^ ((uint32_t)c << 5);
        }

        float acc[4][4][4];
        #pragma unroll
        for (int mf = 0; mf < 4; mf++)
            #pragma unroll
            for (int nf = 0; nf < 4; nf++)
                #pragma unroll
                for (int r = 0; r < 4; r++) acc[mf][nf][r] = 0.f;

        uint32_t soff = 0;
        int cstage = 0, cphase = 0;
        for (int ks = 0; ks < NKS; ks++) {
            mbar_wait(fullb + (uint32_t)cstage * 8u, (uint32_t)cphase);
            #pragma unroll
            for (int c = 0; c < 4; c++) {
                uint32_t a[4][4], bfr[4][2];
                #pragma unroll
                for (int mf = 0; mf < 4; mf++)
                    ldm4(adrA[c] + soff + (uint32_t)mf * 2048u,
                         a[mf][0], a[mf][1], a[mf][2], a[mf][3]);
                #pragma unroll
                for (int p = 0; p < 2; p++) {
                    uint32_t t0, t1, t2, t3;
                    ldm4(adrB[c] + soff + (uint32_t)p * 2048u, t0, t1, t2, t3);
                    bfr[2 * p][0]     = t0; bfr[2 * p][1]     = t2;
                    bfr[2 * p + 1][0] = t1; bfr[2 * p + 1][1] = t3;
                }
                // Early empty-arrive: after the LAST chunk's LDSMs the stage
                // lives entirely in registers.
                if (c == 3) mbar_arrive(emptyb + (uint32_t)cstage * 8u);
                #pragma unroll
                for (int mf = 0; mf < 4; mf++)
                    #pragma unroll
                    for (int nf = 0; nf < 4; nf++)
                        mma_f16(acc[mf][nf], a[mf], bfr[nf]);
            }
            cstage++; soff += STAGE_STRIDE;
            if (cstage == 3) { cstage = 0; soff = 0; cphase ^= 1; }
        }

        // Epilogue: sum_n tanh(acc + tgt[n]) * wv[n]
        const int g = lid >> 2, tig = lid & 3;
        #pragma unroll
        for (int mf = 0; mf < 4; mf++) {
            float p0 = 0.f, p1 = 0.f;
            #pragma unroll
            for (int nf = 0; nf < 4; nf++) {
                int n0 = warp_n * 32 + nf * 8 + 2 * tig;
                float t0 = s_tgt[n0], t1 = s_tgt[n0 + 1];
                float v0 = s_wv[n0],  v1 = s_wv[n0 + 1];
                p0 += fast_tanh(acc[mf][nf][0] + t0) * v0;
                p0 += fast_tanh(acc[mf][nf][1] + t1) * v1;
                p1 += fast_tanh(acc[mf][nf][2] + t0) * v0;
                p1 += fast_tanh(acc[mf][nf][3] + t1) * v1;
            }
            p0 += __shfl_xor_sync(0xFFFFFFFF, p0, 1);
            p0 += __shfl_xor_sync(0xFFFFFFFF, p0, 2);
            p1 += __shfl_xor_sync(0xFFFFFFFF, p1, 1);
            p1 += __shfl_xor_sync(0xFFFFFFFF, p1, 2);
            if (tig == 0) {
                int row = warp_m * 64 + mf * 16 + g;
                s_red[row * 4 + warp_n] = p0;
                s_red[(row + 8) * 4 + warp_n] = p1;
            }
        }
        asm volatile("bar.sync 1, 256;" ::: "memory");   // consumers only
        if (tid < BM) {
            float s = s_red[tid * 4] + s_red[tid * 4 + 1] +
                      s_red[tid * 4 + 2] + s_red[tid * 4 + 3];
            g_score_part[(size_t)bn * M_ + bm * BM + tid] = s;
        }
    }
}

// ---------------------------------------------------------------------------
// Kernel 3: softmax over S per batch
// ---------------------------------------------------------------------------
__global__ __launch_bounds__(1024) void softmax_kernel(float* __restrict__ attn_out)
{
    __shared__ float red[1024];
    const int b = blockIdx.x;
    const int tid = threadIdx.x;

    float s0 = 0.f, s1 = 0.f;
    #pragma unroll
    for (int p = 0; p < NCB; p++) {
        s0 += g_score_part[(size_t)p * M_ + b * S_ + tid];
        s1 += g_score_part[(size_t)p * M_ + b * S_ + 1024 + tid];
    }
    float m = fmaxf(s0, s1);
    red[tid] = m;
    __syncthreads();
    for (int st = 512; st > 0; st >>= 1) {
        if (tid < st) red[tid] = fmaxf(red[tid], red[tid + st]);
        __syncthreads();
    }
    m = red[0];
    __syncthreads();
    float e0 = expf(s0 - m), e1 = expf(s1 - m);
    red[tid] = e0 + e1;
    __syncthreads();
    for (int st = 512; st > 0; st >>= 1) {
        if (tid < st) red[tid] += red[tid + st];
        __syncthreads();
    }
    float inv = 1.f / red[0];
    attn_out[b * S_ + tid] = e0 * inv;
    attn_out[b * S_ + 1024 + tid] = e1 * inv;
}

// ---------------------------------------------------------------------------
// Kernel 4: weighted partials from fp16 context.
// grid (16 s-chunks of 128 rows, 32 b) x 256 — fewer partials, same DRAM floor.
// ---------------------------------------------------------------------------
__global__ __launch_bounds__(256) void weighted_kernel(const float* __restrict__ attn)
{
    const int sc = blockIdx.x;   // 0..15, 128 rows each
    const int b = blockIdx.y;
    const int tid = threadIdx.x;
    float4 acc = make_float4(0.f, 0.f, 0.f, 0.f);
    const uint2* ctx2 = (const uint2*)(g_ctx_h + ((size_t)b * S_ + sc * 128) * D_);
    const float* aw = attn + b * S_ + sc * 128;
    #pragma unroll 4
    for (int s = 0; s < 128; s++) {
        float w = aw[s];
        uint2 v = ctx2[(size_t)s * 256 + tid];
        float2 f0 = __half22float2(*(__half2*)&v.x);
        float2 f1 = __half22float2(*(__half2*)&v.y);
        acc.x += w * f0.x; acc.y += w * f0.y;
        acc.z += w * f1.x; acc.w += w * f1.y;
    }
    float4* dst = (float4*)(g_wpart + ((size_t)sc * B_ + b) * D_);
    dst[tid] = acc;
}

__global__ __launch_bounds__(256) void wreduce_kernel()
{
    int i = blockIdx.x * 256 + threadIdx.x;
    float4 s = make_float4(0.f, 0.f, 0.f, 0.f);
    #pragma unroll
    for (int p = 0; p < 16; p++) {
        float4 v = ((const float4*)g_wpart)[(size_t)p * (B_ * D_ / 4) + i];
        s.x += v.x; s.y += v.y; s.z += v.z; s.w += v.w;
    }
    ((float4*)g_weighted)[i] = s;
}

// ---------------------------------------------------------------------------
// Kernel 5: h_tilde = tanh([weighted, x] @ W_out^T)  — float4 fills (R12)
// ---------------------------------------------------------------------------
__global__ __launch_bounds__(256) void out_kernel(
    const float* __restrict__ x, const float* __restrict__ W_out,
    float* __restrict__ out)
{
    __shared__ float sc[32][132];
    __shared__ float sw[8][132];
    int tid = threadIdx.x;
    int b = tid >> 3, jj = tid & 7;
    int j = blockIdx.x * 8 + jj;
    float acc = 0.f;
    for (int k0 = 0; k0 < 2 * D_; k0 += 128) {
        // sc: 32 rows x 128 cols = 1024 float4, 4 per thread
        #pragma unroll
        for (int i = 0; i < 4; i++) {
            int f = tid + i * 256;
            int r = f >> 5, c4 = f & 31;
            int k = k0 + c4 * 4;
            float4 v = (k < D_)
                ? *(const float4*)(g_weighted + r * D_ + k)
                : *(const float4*)(x + r * D_ + (k - D_));
            *(float4*)&sc[r][c4 * 4] = v;
        }
        // sw: 8 rows x 128 cols = 256 float4, 1 per thread
        {
            int r = tid >> 5, c4 = tid & 31;
            float4 v = *(const float4*)(W_out + (size_t)(blockIdx.x * 8 + r) * (2 * D_) + k0 + c4 * 4);
            *(float4*)&sw[r][c4 * 4] = v;
        }
        __syncthreads();
        #pragma unroll 8
        for (int k = 0; k < 128; k++) acc += sc[b][k] * sw[jj][k];
        __syncthreads();
    }
    out[b * D_ + j] = tanhf(acc);
}

// ---------------------------------------------------------------------------
// Launch. Inputs: x, context, W_in, W_c, b_c, w_v, W_out
// Output: h_tilde [32,1024] then attn_w [32,2048]
// ---------------------------------------------------------------------------
extern "C" void kernel_launch(void* const* d_in, const int* in_sizes, int n_in,
                              void* d_out, int out_size)
{
    const float* x       = (const float*)d_in[0];
    const float* context = (const float*)d_in[1];
    const float* W_in    = (const float*)d_in[2];
    const float* W_c     = (const float*)d_in[3];
    const float* b_c     = (const float*)d_in[4];
    const float* w_v     = (const float*)d_in[5];
    const float* W_out   = (const float*)d_in[6];
    float* out = (float*)d_out;
    float* attn_out = out + B_ * D_;

    cudaFuncSetAttribute(score_gemm_mma,
                         cudaFuncAttributeMaxDynamicSharedMemorySize, SMEM_BYTES);

    prep_kernel<<<PREP_BLOCKS, 256>>>(context, W_c, x, W_in, b_c);
    score_gemm_mma<<<dim3(NCB, M_ / BM), NTHR, SMEM_BYTES>>>(w_v);
    softmax_kernel<<<B_, 1024>>>(attn_out);
    weighted_kernel<<<dim3(16, B_), 256>>>(attn_out);
    wreduce_kernel<<<32, 256>>>();
    out_kernel<<<128, 256>>>(x, W_out, out);
}

// round 15
// speedup vs baseline: 1.0550x; 1.0124x over previous
#include <cuda_runtime.h>
#include <cuda_fp16.h>
#include <cstdint>

// Problem constants
#define B_   32
#define S_   2048
#define D_   1024
#define M_   (B_ * S_)     // 65536
#define NCB  8             // 128-wide column blocks over D

// GEMM tiling (fp16) — R9-proven shape: 128x128 CTA tile, 64x32 warp tile,
// 8 consumer warps + 1 producer warp, mbarrier pipeline, 2 CTA/SM.
#define BM   128
#define BN   128
#define BKH  64            // K halves per stage (128-byte rows)
#define NKS  16            // k-steps per tile
#define NTHR 288           // 8 consumer warps + 1 producer warp

// Scratch (device globals; allocation-free rule)
__device__ float  g_target2[B_ * D_];
__device__ float  g_score_part[NCB * M_];
__device__ float  g_wpart[32 * B_ * D_];
__device__ float  g_weighted[B_ * D_];
__device__ __half g_ctx_h[(size_t)M_ * D_];   // 128MB fp16 context
__device__ __half g_wc_h[D_ * D_];            // 2MB fp16 W_c

// ---------------------------------------------------------------------------
// PTX helpers (generic sm_80/90 subset only — no tcgen05 on compute_103 PTX)
// ---------------------------------------------------------------------------
__device__ __forceinline__ uint32_t smem_u32(const void* p) {
    uint32_t a;
    asm("{ .reg .u64 t; cvta.to.shared.u64 t, %1; cvt.u32.u64 %0, t; }"
        : "=r"(a) : "l"(p));
    return a;
}

__device__ __forceinline__ void cp16(uint32_t saddr, const void* gaddr) {
    asm volatile("cp.async.cg.shared.global [%0], [%1], 16;"
                 :: "r"(saddr), "l"(gaddr));
}

__device__ __forceinline__ void ldm4(uint32_t addr, uint32_t& r0, uint32_t& r1,
                                     uint32_t& r2, uint32_t& r3) {
    asm volatile("ldmatrix.sync.aligned.m8n8.x4.shared.b16 {%0,%1,%2,%3}, [%4];"
                 : "=r"(r0), "=r"(r1), "=r"(r2), "=r"(r3) : "r"(addr));
}

__device__ __forceinline__ void mma_f16(float* d, const uint32_t* a, const uint32_t* b) {
    asm volatile(
        "mma.sync.aligned.m16n8k16.row.col.f32.f16.f16.f32 "
        "{%0,%1,%2,%3}, {%4,%5,%6,%7}, {%8,%9}, {%0,%1,%2,%3};"
        : "+f"(d[0]), "+f"(d[1]), "+f"(d[2]), "+f"(d[3])
        : "r"(a[0]), "r"(a[1]), "r"(a[2]), "r"(a[3]), "r"(b[0]), "r"(b[1]));
}

__device__ __forceinline__ float fast_tanh(float x) {
    float y;
    asm("tanh.approx.f32 %0, %1;" : "=f"(y) : "f"(x));
    return y;
}

__device__ __forceinline__ void mbar_init(uint32_t a, uint32_t n) {
    asm volatile("mbarrier.init.shared.b64 [%0], %1;" :: "r"(a), "r"(n) : "memory");
}

__device__ __forceinline__ void mbar_arrive(uint32_t a) {
    asm volatile("mbarrier.arrive.shared.b64 _, [%0];" :: "r"(a) : "memory");
}

__device__ __forceinline__ void cp_arrive_noinc(uint32_t a) {
    asm volatile("cp.async.mbarrier.arrive.noinc.shared.b64 [%0];"
                 :: "r"(a) : "memory");
}

__device__ __forceinline__ void mbar_wait(uint32_t mbar, uint32_t parity) {
    uint32_t done;
    asm volatile(
        "{\n\t.reg .pred p;\n\t"
        "mbarrier.try_wait.parity.acquire.cta.shared::cta.b64 p, [%1], %2;\n\t"
        "selp.b32 %0, 1, 0, p;\n\t}"
        : "=r"(done) : "r"(mbar), "r"(parity) : "memory");
    if (!done) {
        asm volatile(
            "{\n\t.reg .pred P1;\n\t"
            "WL%=:\n\t"
            "mbarrier.try_wait.parity.acquire.cta.shared::cta.b64 P1, [%0], %1, 0x989680;\n\t"
            "@P1 bra.uni WD%=;\n\t"
            "bra.uni WL%=;\n\t"
            "WD%=:\n\t}"
            :: "r"(mbar), "r"(parity) : "memory");
    }
}

// ---------------------------------------------------------------------------
// Kernel 0: fused prep — target blocks (0..127) + fp16 conversion (32B/thread).
// ---------------------------------------------------------------------------
#define TGT_BLOCKS 128
#define CTX_BLOCKS ((int)((size_t)M_ * D_ / 8 / 256))   // 32768
#define WC_BLOCKS  (D_ * D_ / 8 / 256)                  // 512
#define PREP_BLOCKS (TGT_BLOCKS + CTX_BLOCKS + WC_BLOCKS)

__global__ __launch_bounds__(256) void prep_kernel(
    const float* __restrict__ ctx, const float* __restrict__ wc,
    const float* __restrict__ x, const float* __restrict__ W_in,
    const float* __restrict__ b_c)
{
    __shared__ float sx[32][129];
    __shared__ float sw[8][129];
    const int bid = blockIdx.x;
    const int tid = threadIdx.x;

    if (bid < TGT_BLOCKS) {
        // ---- target2[b][j] = sum_k x[b][k] * W_in[j][k] + b_c[j] ----
        int b = tid >> 3, jj = tid & 7;
        int j = bid * 8 + jj;
        float acc = 0.f;
        for (int k0 = 0; k0 < D_; k0 += 128) {
            #pragma unroll
            for (int i = 0; i < 16; i++) {
                int f = tid + i * 256;
                int r = f >> 7, c = f & 127;
                sx[r][c] = x[r * D_ + k0 + c];
            }
            #pragma unroll
            for (int i = 0; i < 4; i++) {
                int f = tid + i * 256;
                int r = f >> 7, c = f & 127;
                sw[r][c] = W_in[(size_t)(bid * 8 + r) * D_ + k0 + c];
            }
            __syncthreads();
            #pragma unroll 8
            for (int k = 0; k < 128; k++) acc += sx[b][k] * sw[jj][k];
            __syncthreads();
        }
        g_target2[b * D_ + j] = acc + b_c[j];
    } else {
        // ---- fp32 -> fp16 conversion, 8 floats (32B) per thread ----
        int cb = bid - TGT_BLOCKS;
        const float* src;
        __half* dst;
        size_t i;
        if (cb < CTX_BLOCKS) {
            i = ((size_t)cb * 256 + tid) * 8;
            src = ctx; dst = g_ctx_h;
        } else {
            i = ((size_t)(cb - CTX_BLOCKS) * 256 + tid) * 8;
            src = wc; dst = g_wc_h;
        }
        float4 v0 = *(const float4*)(src + i);
        float4 v1 = *(const float4*)(src + i + 4);
        __half2 h0 = __floats2half2_rn(v0.x, v0.y);
        __half2 h1 = __floats2half2_rn(v0.z, v0.w);
        __half2 h2 = __floats2half2_rn(v1.x, v1.y);
        __half2 h3 = __floats2half2_rn(v1.z, v1.w);
        uint4 o;
        o.x = *(uint32_t*)&h0; o.y = *(uint32_t*)&h1;
        o.z = *(uint32_t*)&h2; o.w = *(uint32_t*)&h3;
        *(uint4*)(dst + i) = o;
    }
}

// ---------------------------------------------------------------------------
// Kernel 2: warp-specialized fp16 mma score GEMM (R12 exact).
// ---------------------------------------------------------------------------
// smem (from 1024-aligned base):
//   0: s_tgt[128]  512: s_wv[128]  1024: s_red[512 floats]
//   3072: full[3] mbars  3104: empty[3] mbars  4096: tiles (3 x 32KB)
#define OFF_TILE     4096
#define STAGE_STRIDE 32768
#define SMEM_NEED    (OFF_TILE + 3 * STAGE_STRIDE)
#define SMEM_BYTES   (SMEM_NEED + 1024)

__global__ __launch_bounds__(NTHR, 2) void score_gemm_mma(
    const float* __restrict__ w_v)
{
    extern __shared__ char dynsmem[];
    uint32_t sbm = smem_u32(dynsmem);
    uint32_t ab = (sbm + 1023u) & ~1023u;
    char* abp = dynsmem + (ab - sbm);

    const int bn = blockIdx.x;       // 0..7 (fast dim -> A-tile L2 sharing)
    const int bm = blockIdx.y;       // 0..511
    const int tid = threadIdx.x;
    const int wid = tid >> 5, lid = tid & 31;
    const int b = bm >> 4;

    float* s_tgt = (float*)(abp);
    float* s_wv  = (float*)(abp + 512);
    float* s_red = (float*)(abp + 1024);
    const uint32_t fullb  = ab + 3072;
    const uint32_t emptyb = ab + 3104;
    const uint32_t tbase = ab + OFF_TILE;

    if (tid == 0) {
        #pragma unroll
        for (int s = 0; s < 3; s++) {
            mbar_init(fullb + s * 8u, 32);    // producer lanes (cp-completion)
            mbar_init(emptyb + s * 8u, 256);  // consumer threads
        }
    }
    if (tid < 128) {
        s_tgt[tid] = g_target2[b * D_ + bn * BN + tid];
        s_wv[tid]  = w_v[bn * BN + tid];
    }
    __syncthreads();   // all 288: mbar init + s_tgt visible

    if (wid == 8) {
        // ---------------- producer warp ----------------
        const int r0 = lid >> 3;                       // 0..3
        const int kq = lid & 7;
        const uint32_t swzE = ((uint32_t)kq * 16) ^ ((uint32_t)r0 << 4);
        const uint32_t sEA = tbase + (uint32_t)r0 * 128 + swzE;
        const uint32_t sOA = (sEA ^ 64u) + 512u;
        const uint32_t sEB = sEA + 16384u;
        const uint32_t sOB = sOA + 16384u;
        const __half* gA = g_ctx_h + (size_t)bm * BM * D_ + (size_t)r0 * D_ + kq * 8;
        const __half* gB = g_wc_h + (size_t)bn * BN * D_ + (size_t)r0 * D_ + kq * 8;

        uint32_t pslot = 0;
        int pstage = 0, pphase = 1;   // phase=1: first 3 empty-waits pass
        for (int ks = 0; ks < NKS; ks++) {
            mbar_wait(emptyb + (uint32_t)pstage * 8u, (uint32_t)pphase);
            #pragma unroll
            for (int j = 0; j < 16; j++) {
                cp16(sEA + pslot + (uint32_t)j * 1024u, gA + (size_t)j * 8192);
                cp16(sOA + pslot + (uint32_t)j * 1024u, gA + (size_t)j * 8192 + 4096);
                cp16(sEB + pslot + (uint32_t)j * 1024u, gB + (size_t)j * 8192);
                cp16(sOB + pslot + (uint32_t)j * 1024u, gB + (size_t)j * 8192 + 4096);
            }
            cp_arrive_noinc(fullb + (uint32_t)pstage * 8u);
            gA += BKH; gB += BKH;
            pstage++; pslot += STAGE_STRIDE;
            if (pstage == 3) { pstage = 0; pslot = 0; pphase ^= 1; }
        }
    } else {
        // ---------------- consumer warps ----------------
        const int warp_m = wid & 1;
        const int warp_n = wid >> 1;
        const int r15 = lid & 15, q = lid >> 4;
        const uint32_t swz = ((uint32_t)(r15 & 7)) << 4;
        const uint32_t loffA = (uint32_t)((warp_m * 64 + r15) * 128) + (((uint32_t)q * 16) ^ swz);
        const uint32_t loffB = (uint32_t)((warp_n * 32 + r15) * 128) + (((uint32_t)q * 16) ^ swz) + 16384u;
        uint32_t adrA[4], adrB[4];
        #pragma unroll
        for (int c = 0; c < 4; c++) {
            adrA[c] = (tbase + loffA) ^ ((uint32_t)c << 5);
            adrB[c] = (tbase + loffB) ^ ((uint32_t)c << 5);
        }

        float acc[4][4][4];
        #pragma unroll
        for (int mf = 0; mf < 4; mf++)
            #pragma unroll
            for (int nf = 0; nf < 4; nf++)
                #pragma unroll
                for (int r = 0; r < 4; r++) acc[mf][nf][r] = 0.f;

        uint32_t soff = 0;
        int cstage = 0, cphase = 0;
        for (int ks = 0; ks < NKS; ks++) {
            mbar_wait(fullb + (uint32_t)cstage * 8u, (uint32_t)cphase);
            #pragma unroll
            for (int c = 0; c < 4; c++) {
                uint32_t a[4][4], bfr[4][2];
                #pragma unroll
                for (int mf = 0; mf < 4; mf++)
                    ldm4(adrA[c] + soff + (uint32_t)mf * 2048u,
                         a[mf][0], a[mf][1], a[mf][2], a[mf][3]);
                #pragma unroll
                for (int p = 0; p < 2; p++) {
                    uint32_t t0, t1, t2, t3;
                    ldm4(adrB[c] + soff + (uint32_t)p * 2048u, t0, t1, t2, t3);
                    bfr[2 * p][0]     = t0; bfr[2 * p][1]     = t2;
                    bfr[2 * p + 1][0] = t1; bfr[2 * p + 1][1] = t3;
                }
                // Early empty-arrive: after the LAST chunk's LDSMs the stage
                // lives entirely in registers.
                if (c == 3) mbar_arrive(emptyb + (uint32_t)cstage * 8u);
                #pragma unroll
                for (int mf = 0; mf < 4; mf++)
                    #pragma unroll
                    for (int nf = 0; nf < 4; nf++)
                        mma_f16(acc[mf][nf], a[mf], bfr[nf]);
            }
            cstage++; soff += STAGE_STRIDE;
            if (cstage == 3) { cstage = 0; soff = 0; cphase ^= 1; }
        }

        // Epilogue: sum_n tanh(acc + tgt[n]) * wv[n]
        const int g = lid >> 2, tig = lid & 3;
        #pragma unroll
        for (int mf = 0; mf < 4; mf++) {
            float p0 = 0.f, p1 = 0.f;
            #pragma unroll
            for (int nf = 0; nf < 4; nf++) {
                int n0 = warp_n * 32 + nf * 8 + 2 * tig;
                float t0 = s_tgt[n0], t1 = s_tgt[n0 + 1];
                float v0 = s_wv[n0],  v1 = s_wv[n0 + 1];
                p0 += fast_tanh(acc[mf][nf][0] + t0) * v0;
                p0 += fast_tanh(acc[mf][nf][1] + t1) * v1;
                p1 += fast_tanh(acc[mf][nf][2] + t0) * v0;
                p1 += fast_tanh(acc[mf][nf][3] + t1) * v1;
            }
            p0 += __shfl_xor_sync(0xFFFFFFFF, p0, 1);
            p0 += __shfl_xor_sync(0xFFFFFFFF, p0, 2);
            p1 += __shfl_xor_sync(0xFFFFFFFF, p1, 1);
            p1 += __shfl_xor_sync(0xFFFFFFFF, p1, 2);
            if (tig == 0) {
                int row = warp_m * 64 + mf * 16 + g;
                s_red[row * 4 + warp_n] = p0;
                s_red[(row + 8) * 4 + warp_n] = p1;
            }
        }
        asm volatile("bar.sync 1, 256;" ::: "memory");   // consumers only
        if (tid < BM) {
            float s = s_red[tid * 4] + s_red[tid * 4 + 1] +
                      s_red[tid * 4 + 2] + s_red[tid * 4 + 3];
            g_score_part[(size_t)bn * M_ + bm * BM + tid] = s;
        }
    }
}

// ---------------------------------------------------------------------------
// Kernel 3: softmax over S per batch (__expf)
// ---------------------------------------------------------------------------
__global__ __launch_bounds__(1024) void softmax_kernel(float* __restrict__ attn_out)
{
    __shared__ float red[1024];
    const int b = blockIdx.x;
    const int tid = threadIdx.x;

    float s0 = 0.f, s1 = 0.f;
    #pragma unroll
    for (int p = 0; p < NCB; p++) {
        s0 += g_score_part[(size_t)p * M_ + b * S_ + tid];
        s1 += g_score_part[(size_t)p * M_ + b * S_ + 1024 + tid];
    }
    float m = fmaxf(s0, s1);
    red[tid] = m;
    __syncthreads();
    for (int st = 512; st > 0; st >>= 1) {
        if (tid < st) red[tid] = fmaxf(red[tid], red[tid + st]);
        __syncthreads();
    }
    m = red[0];
    __syncthreads();
    float e0 = __expf(s0 - m), e1 = __expf(s1 - m);
    red[tid] = e0 + e1;
    __syncthreads();
    for (int st = 512; st > 0; st >>= 1) {
        if (tid < st) red[tid] += red[tid + st];
        __syncthreads();
    }
    float inv = 1.f / red[0];
    attn_out[b * S_ + tid] = e0 * inv;
    attn_out[b * S_ + 1024 + tid] = e1 * inv;
}

// ---------------------------------------------------------------------------
// Kernel 4: weighted partials from fp16 context.
// grid (32 s-chunks of 64 rows, 32 b) x 256 — interior optimum on the
// weighted-MLP vs wreduce-traffic tradeoff (2048 CTAs too many partials,
// 512 CTAs too little DRAM MLP).
// ---------------------------------------------------------------------------
__global__ __launch_bounds__(256) void weighted_kernel(const float* __restrict__ attn)
{
    const int sc = blockIdx.x;   // 0..31, 64 rows each
    const int b = blockIdx.y;
    const int tid = threadIdx.x;
    float4 acc = make_float4(0.f, 0.f, 0.f, 0.f);
    const uint2* ctx2 = (const uint2*)(g_ctx_h + ((size_t)b * S_ + sc * 64) * D_);
    const float* aw = attn + b * S_ + sc * 64;
    #pragma unroll 4
    for (int s = 0; s < 64; s++) {
        float w = aw[s];
        uint2 v = ctx2[(size_t)s * 256 + tid];
        float2 f0 = __half22float2(*(__half2*)&v.x);
        float2 f1 = __half22float2(*(__half2*)&v.y);
        acc.x += w * f0.x; acc.y += w * f0.y;
        acc.z += w * f1.x; acc.w += w * f1.y;
    }
    float4* dst = (float4*)(g_wpart + ((size_t)sc * B_ + b) * D_);
    dst[tid] = acc;
}

__global__ __launch_bounds__(256) void wreduce_kernel()
{
    int i = blockIdx.x * 256 + threadIdx.x;
    float4 s = make_float4(0.f, 0.f, 0.f, 0.f);
    #pragma unroll
    for (int p = 0; p < 32; p++) {
        float4 v = ((const float4*)g_wpart)[(size_t)p * (B_ * D_ / 4) + i];
        s.x += v.x; s.y += v.y; s.z += v.z; s.w += v.w;
    }
    ((float4*)g_weighted)[i] = s;
}

// ---------------------------------------------------------------------------
// Kernel 5: h_tilde = tanh([weighted, x] @ W_out^T)  — float4 fills (R12)
// ---------------------------------------------------------------------------
__global__ __launch_bounds__(256) void out_kernel(
    const float* __restrict__ x, const float* __restrict__ W_out,
    float* __restrict__ out)
{
    __shared__ float sc[32][132];
    __shared__ float sw[8][132];
    int tid = threadIdx.x;
    int b = tid >> 3, jj = tid & 7;
    int j = blockIdx.x * 8 + jj;
    float acc = 0.f;
    for (int k0 = 0; k0 < 2 * D_; k0 += 128) {
        // sc: 32 rows x 128 cols = 1024 float4, 4 per thread
        #pragma unroll
        for (int i = 0; i < 4; i++) {
            int f = tid + i * 256;
            int r = f >> 5, c4 = f & 31;
            int k = k0 + c4 * 4;
            float4 v = (k < D_)
                ? *(const float4*)(g_weighted + r * D_ + k)
                : *(const float4*)(x + r * D_ + (k - D_));
            *(float4*)&sc[r][c4 * 4] = v;
        }
        // sw: 8 rows x 128 cols = 256 float4, 1 per thread
        {
            int r = tid >> 5, c4 = tid & 31;
            float4 v = *(const float4*)(W_out + (size_t)(blockIdx.x * 8 + r) * (2 * D_) + k0 + c4 * 4);
            *(float4*)&sw[r][c4 * 4] = v;
        }
        __syncthreads();
        #pragma unroll 8
        for (int k = 0; k < 128; k++) acc += sc[b][k] * sw[jj][k];
        __syncthreads();
    }
    out[b * D_ + j] = tanhf(acc);
}

// ---------------------------------------------------------------------------
// Launch. Inputs: x, context, W_in, W_c, b_c, w_v, W_out
// Output: h_tilde [32,1024] then attn_w [32,2048]
// ---------------------------------------------------------------------------
extern "C" void kernel_launch(void* const* d_in, const int* in_sizes, int n_in,
                              void* d_out, int out_size)
{
    const float* x       = (const float*)d_in[0];
    const float* context = (const float*)d_in[1];
    const float* W_in    = (const float*)d_in[2];
    const float* W_c     = (const float*)d_in[3];
    const float* b_c     = (const float*)d_in[4];
    const float* w_v     = (const float*)d_in[5];
    const float* W_out   = (const float*)d_in[6];
    float* out = (float*)d_out;
    float* attn_out = out + B_ * D_;

    cudaFuncSetAttribute(score_gemm_mma,
                         cudaFuncAttributeMaxDynamicSharedMemorySize, SMEM_BYTES);

    prep_kernel<<<PREP_BLOCKS, 256>>>(context, W_c, x, W_in, b_c);
    score_gemm_mma<<<dim3(NCB, M_ / BM), NTHR, SMEM_BYTES>>>(w_v);
    softmax_kernel<<<B_, 1024>>>(attn_out);
    weighted_kernel<<<dim3(32, B_), 256>>>(attn_out);
    wreduce_kernel<<<32, 256>>>();
    out_kernel<<<128, 256>>>(x, W_out, out);
}